// round 1
// baseline (speedup 1.0000x reference)
#include <cuda_runtime.h>
#include <math.h>

#define EPSBN 1e-5f

// Problem dims (fixed)
#define B_    64
#define CIN   1024
#define P_    512
#define COUT  2048
#define NSP   256      // W*H = 16*16
#define HEADS 4
#define DH    128      // P_/HEADS

// ---------------- scratch (static __device__, no allocs) ----------------
__device__ __align__(16) float d_w1s [P_  * CIN ];
__device__ __align__(16) float d_w3s [COUT* P_  ];
__device__ __align__(16) float d_wscs[COUT* CIN ];
__device__ __align__(16) float d_t1    [P_ ];
__device__ __align__(16) float d_vscale[P_ ];
__device__ __align__(16) float d_vshift[P_ ];
__device__ __align__(16) float d_tfin  [COUT];
__device__ __align__(16) float d_pos [HEADS * DH * NSP];
__device__ __align__(16) float d_out1[B_ * P_ * NSP];
__device__ __align__(16) float d_qb  [B_ * P_ * NSP];
__device__ __align__(16) float d_kb  [B_ * P_ * NSP];
__device__ __align__(16) float d_vb  [B_ * P_ * NSP];
__device__ __align__(16) float d_attn[B_ * HEADS * NSP * NSP];
__device__ __align__(16) float d_attout[B_ * P_ * NSP];

// ---------------- generic tiled GEMM (fp32) ----------------
#define BK 16
#define BM 128
#define BN 128
#define LDSP 132   // padded smem row stride

// KMAJ=true : G is [K][dim] (k slow), load float4 along dim, store direct
// KMAJ=false: G is [dim][K] (k fast), load float4 along k, transpose on store
template<bool KMAJ>
__device__ __forceinline__ void load_tile(float* __restrict__ S,
                                          const float* __restrict__ G,
                                          int ldg, int base, int k0, int tid) {
    if (KMAJ) {
#pragma unroll
        for (int it = 0; it < 2; ++it) {
            int idx = tid + it * 256;       // 0..511 for 16x128 tile
            int r = idx >> 5;               // k row 0..15
            int c = (idx & 31) << 2;        // dim col 0..124
            float4 v = *reinterpret_cast<const float4*>(G + (long)(k0 + r) * ldg + base + c);
            *reinterpret_cast<float4*>(S + r * LDSP + c) = v;
        }
    } else {
#pragma unroll
        for (int it = 0; it < 2; ++it) {
            int idx = tid + it * 256;
            int r = idx >> 2;               // dim row 0..127
            int c = (idx & 3) << 2;         // k col 0..12
            float4 v = *reinterpret_cast<const float4*>(G + (long)(base + r) * ldg + k0 + c);
            S[(c + 0) * LDSP + r] = v.x;
            S[(c + 1) * LDSP + r] = v.y;
            S[(c + 2) * LDSP + r] = v.z;
            S[(c + 3) * LDSP + r] = v.w;
        }
    }
}

__device__ __forceinline__ void mma_step(const float* __restrict__ As,
                                         const float* __restrict__ Bs,
                                         float (&acc)[8][8], int tr, int tc) {
#pragma unroll
    for (int kk = 0; kk < BK; ++kk) {
        float a[8], b[8];
        *reinterpret_cast<float4*>(a)     = *reinterpret_cast<const float4*>(As + kk * LDSP + tr * 8);
        *reinterpret_cast<float4*>(a + 4) = *reinterpret_cast<const float4*>(As + kk * LDSP + tr * 8 + 4);
        *reinterpret_cast<float4*>(b)     = *reinterpret_cast<const float4*>(Bs + kk * LDSP + tc * 8);
        *reinterpret_cast<float4*>(b + 4) = *reinterpret_cast<const float4*>(Bs + kk * LDSP + tc * 8 + 4);
#pragma unroll
        for (int i = 0; i < 8; ++i)
#pragma unroll
            for (int j = 0; j < 8; ++j)
                acc[i][j] = fmaf(a[i], b[j], acc[i][j]);
    }
}

// C[z][m][n] = act( (phase1 + phase2 dot products) * scale[m] + shift[m] )
// C row stride is always 256 (=NSP or attn row).
template<bool AKM1, bool BKM1, bool AKM2, bool BKM2, bool RELU, bool HAS2>
__global__ void __launch_bounds__(256, 2)
gemm_kernel(const float* __restrict__ A1, int lda1, long sA1,
            const float* __restrict__ B1, int ldb1, long sB1, int K1,
            const float* __restrict__ A2, int lda2, long sA2, int aMod2,
            const float* __restrict__ B2, int ldb2, long sB2, int K2,
            float* __restrict__ C, long sC,
            const float* __restrict__ scale, const float* __restrict__ shift) {
    __shared__ __align__(16) float As[BK * LDSP];
    __shared__ __align__(16) float Bs[BK * LDSP];
    const int z  = blockIdx.z;
    const int m0 = blockIdx.y * BM;
    const int n0 = blockIdx.x * BN;
    const int tid = threadIdx.x;
    const int tr = tid >> 4;
    const int tc = tid & 15;

    float acc[8][8];
#pragma unroll
    for (int i = 0; i < 8; ++i)
#pragma unroll
        for (int j = 0; j < 8; ++j) acc[i][j] = 0.0f;

    {
        const float* Az = A1 + (long)z * sA1;
        const float* Bz = B1 + (long)z * sB1;
        for (int k0 = 0; k0 < K1; k0 += BK) {
            __syncthreads();
            load_tile<AKM1>(As, Az, lda1, m0, k0, tid);
            load_tile<BKM1>(Bs, Bz, ldb1, n0, k0, tid);
            __syncthreads();
            mma_step(As, Bs, acc, tr, tc);
        }
    }
    if (HAS2) {
        const float* Az = A2 + (long)(aMod2 ? (z % aMod2) : z) * sA2;
        const float* Bz = B2 + (long)z * sB2;
        for (int k0 = 0; k0 < K2; k0 += BK) {
            __syncthreads();
            load_tile<AKM2>(As, Az, lda2, m0, k0, tid);
            load_tile<BKM2>(Bs, Bz, ldb2, n0, k0, tid);
            __syncthreads();
            mma_step(As, Bs, acc, tr, tc);
        }
    }

#pragma unroll
    for (int i = 0; i < 8; ++i) {
        int row = m0 + tr * 8 + i;
        float s = scale ? __ldg(scale + row) : 1.0f;
        float t = shift ? __ldg(shift + row) : 0.0f;
        float outv[8];
#pragma unroll
        for (int j = 0; j < 8; ++j) {
            float vv = fmaf(acc[i][j], s, t);
            if (RELU) vv = fmaxf(vv, 0.0f);
            outv[j] = vv;
        }
        float* cp = C + (long)z * sC + (long)row * 256 + n0 + tc * 8;
        *reinterpret_cast<float4*>(cp)     = *reinterpret_cast<float4*>(outv);
        *reinterpret_cast<float4*>(cp + 4) = *reinterpret_cast<float4*>(outv + 4);
    }
}

// ---------------- small kernels ----------------
__global__ void scale_w_kernel(const float* __restrict__ w, const float* __restrict__ g,
                               const float* __restrict__ var, float* __restrict__ out,
                               int total, int C) {
    int idx = blockIdx.x * blockDim.x + threadIdx.x;
    if (idx >= total) return;
    int o = idx / C;
    out[idx] = w[idx] * (g[o] / sqrtf(var[o] + EPSBN));
}

__global__ void prep_vec_kernel(const float* bn1_g, const float* bn1_b, const float* bn1_m, const float* bn1_v,
                                const float* bn2_g, const float* bn2_b, const float* bn2_m, const float* bn2_v,
                                const float* v_b,
                                const float* bn3_g, const float* bn3_b, const float* bn3_m, const float* bn3_v,
                                const float* sc_b,
                                const float* scbn_g, const float* scbn_b, const float* scbn_m, const float* scbn_v) {
    int i = blockIdx.x * blockDim.x + threadIdx.x;
    if (i < P_) {
        float s1 = bn1_g[i] / sqrtf(bn1_v[i] + EPSBN);
        d_t1[i] = bn1_b[i] - bn1_m[i] * s1;
        float s2 = bn2_g[i] / sqrtf(bn2_v[i] + EPSBN);
        float t2 = bn2_b[i] - bn2_m[i] * s2;
        d_vscale[i] = s2;
        d_vshift[i] = fmaf(v_b[i], s2, t2);   // BN2 folded into V (softmax rows sum to 1)
    }
    if (i < COUT) {
        float s3 = bn3_g[i] / sqrtf(bn3_v[i] + EPSBN);
        float t3 = bn3_b[i] - bn3_m[i] * s3;
        float ss = scbn_g[i] / sqrtf(scbn_v[i] + EPSBN);
        float tsc = fmaf(sc_b[i] - scbn_m[i], ss, scbn_b[i]);
        d_tfin[i] = t3 + tsc;
    }
}

__global__ void pos_kernel(const float* __restrict__ rel_h, const float* __restrict__ rel_w) {
    int idx = blockIdx.x * blockDim.x + threadIdx.x;
    if (idx >= HEADS * DH * NSP) return;
    int n  = idx & 255;        // n = w*16 + h'
    int hd = idx >> 8;         // h*DH + d
    int w  = n >> 4;
    int hh = n & 15;
    d_pos[idx] = rel_h[hd * 16 + hh] + rel_w[hd * 16 + w];
}

// 256-wide row softmax, one warp per row
__global__ void softmax256_kernel(float* __restrict__ a) {
    int warp = (blockIdx.x * blockDim.x + threadIdx.x) >> 5;
    int lane = threadIdx.x & 31;
    float* row = a + (long)warp * 256;
    float v[8];
    float mx = -INFINITY;
#pragma unroll
    for (int j = 0; j < 8; ++j) { v[j] = row[lane + j * 32]; mx = fmaxf(mx, v[j]); }
#pragma unroll
    for (int o = 16; o; o >>= 1) mx = fmaxf(mx, __shfl_xor_sync(0xffffffffu, mx, o));
    float s = 0.0f;
#pragma unroll
    for (int j = 0; j < 8; ++j) { v[j] = __expf(v[j] - mx); s += v[j]; }
#pragma unroll
    for (int o = 16; o; o >>= 1) s += __shfl_xor_sync(0xffffffffu, s, o);
    float inv = 1.0f / s;
#pragma unroll
    for (int j = 0; j < 8; ++j) row[lane + j * 32] = v[j] * inv;
}

// ---------------- launch ----------------
extern "C" void kernel_launch(void* const* d_in, const int* in_sizes, int n_in,
                              void* d_out, int out_size) {
    const float* x       = (const float*)d_in[0];
    const float* conv1_w = (const float*)d_in[1];
    const float* bn1_g = (const float*)d_in[2];
    const float* bn1_b = (const float*)d_in[3];
    const float* bn1_m = (const float*)d_in[4];
    const float* bn1_v = (const float*)d_in[5];
    const float* q_w = (const float*)d_in[6];
    const float* q_b = (const float*)d_in[7];
    const float* k_w = (const float*)d_in[8];
    const float* k_b = (const float*)d_in[9];
    const float* v_w = (const float*)d_in[10];
    const float* v_b = (const float*)d_in[11];
    const float* rel_h = (const float*)d_in[12];
    const float* rel_w = (const float*)d_in[13];
    const float* bn2_g = (const float*)d_in[14];
    const float* bn2_b = (const float*)d_in[15];
    const float* bn2_m = (const float*)d_in[16];
    const float* bn2_v = (const float*)d_in[17];
    const float* conv3_w = (const float*)d_in[18];
    const float* bn3_g = (const float*)d_in[19];
    const float* bn3_b = (const float*)d_in[20];
    const float* bn3_m = (const float*)d_in[21];
    const float* bn3_v = (const float*)d_in[22];
    const float* sc_w  = (const float*)d_in[23];
    const float* sc_b  = (const float*)d_in[24];
    const float* scbn_g = (const float*)d_in[25];
    const float* scbn_b = (const float*)d_in[26];
    const float* scbn_m = (const float*)d_in[27];
    const float* scbn_v = (const float*)d_in[28];
    float* out = (float*)d_out;

    float *w1s, *w3s, *wscs, *t1, *vscale, *vshift, *tfin, *pos;
    float *out1, *qb, *kb, *vb, *attn, *attout;
    cudaGetSymbolAddress((void**)&w1s,   d_w1s);
    cudaGetSymbolAddress((void**)&w3s,   d_w3s);
    cudaGetSymbolAddress((void**)&wscs,  d_wscs);
    cudaGetSymbolAddress((void**)&t1,    d_t1);
    cudaGetSymbolAddress((void**)&vscale,d_vscale);
    cudaGetSymbolAddress((void**)&vshift,d_vshift);
    cudaGetSymbolAddress((void**)&tfin,  d_tfin);
    cudaGetSymbolAddress((void**)&pos,   d_pos);
    cudaGetSymbolAddress((void**)&out1,  d_out1);
    cudaGetSymbolAddress((void**)&qb,    d_qb);
    cudaGetSymbolAddress((void**)&kb,    d_kb);
    cudaGetSymbolAddress((void**)&vb,    d_vb);
    cudaGetSymbolAddress((void**)&attn,  d_attn);
    cudaGetSymbolAddress((void**)&attout,d_attout);

    // ---- prep: fold BN into weights / vectors ----
    scale_w_kernel<<<(P_ * CIN + 255) / 256, 256>>>(conv1_w, bn1_g, bn1_v, w1s, P_ * CIN, CIN);
    scale_w_kernel<<<(COUT * P_ + 255) / 256, 256>>>(conv3_w, bn3_g, bn3_v, w3s, COUT * P_, P_);
    scale_w_kernel<<<(COUT * CIN + 255) / 256, 256>>>(sc_w, scbn_g, scbn_v, wscs, COUT * CIN, CIN);
    prep_vec_kernel<<<(COUT + 255) / 256, 256>>>(bn1_g, bn1_b, bn1_m, bn1_v,
                                                 bn2_g, bn2_b, bn2_m, bn2_v, v_b,
                                                 bn3_g, bn3_b, bn3_m, bn3_v, sc_b,
                                                 scbn_g, scbn_b, scbn_m, scbn_v);
    pos_kernel<<<(HEADS * DH * NSP + 255) / 256, 256>>>(rel_h, rel_w);

    // ---- conv1 + BN1 + ReLU : out1[b][p][n] ----
    gemm_kernel<false, true, false, true, true, false><<<dim3(2, 4, B_), 256>>>(
        w1s, CIN, 0, x, NSP, (long)CIN * NSP, CIN,
        nullptr, 0, 0, 0, nullptr, 0, 0, 0,
        out1, (long)P_ * NSP, nullptr, t1);

    // ---- q, k, v (v has BN2 folded in) ----
    gemm_kernel<false, true, false, true, false, false><<<dim3(2, 4, B_), 256>>>(
        q_w, P_, 0, out1, NSP, (long)P_ * NSP, P_,
        nullptr, 0, 0, 0, nullptr, 0, 0, 0,
        qb, (long)P_ * NSP, nullptr, q_b);
    gemm_kernel<false, true, false, true, false, false><<<dim3(2, 4, B_), 256>>>(
        k_w, P_, 0, out1, NSP, (long)P_ * NSP, P_,
        nullptr, 0, 0, 0, nullptr, 0, 0, 0,
        kb, (long)P_ * NSP, nullptr, k_b);
    gemm_kernel<false, true, false, true, false, false><<<dim3(2, 4, B_), 256>>>(
        v_w, P_, 0, out1, NSP, (long)P_ * NSP, P_,
        nullptr, 0, 0, 0, nullptr, 0, 0, 0,
        vb, (long)P_ * NSP, vscale, vshift);

    // ---- logits L[n][m] = Q^T K + pos^T Q per (b,h) ----
    gemm_kernel<true, true, true, true, false, true><<<dim3(2, 2, B_ * HEADS), 256>>>(
        qb, NSP, (long)DH * NSP, kb, NSP, (long)DH * NSP, DH,
        pos, NSP, (long)DH * NSP, HEADS,
        qb, NSP, (long)DH * NSP, DH,
        attn, (long)NSP * NSP, nullptr, nullptr);

    // ---- softmax over m (rows of 256) ----
    softmax256_kernel<<<(B_ * HEADS * NSP) / 8, 256>>>(attn);

    // ---- out[d][n] = V' · A^T, epilogue = ReLU (BN2 already in V') ----
    gemm_kernel<false, false, false, false, true, false><<<dim3(2, 1, B_ * HEADS), 256>>>(
        vb, NSP, (long)DH * NSP, attn, NSP, (long)NSP * NSP, NSP,
        nullptr, 0, 0, 0, nullptr, 0, 0, 0,
        attout, (long)DH * NSP, nullptr, nullptr);

    // ---- conv3+BN3 + shortcut+scBN + add + ReLU, fused two-phase GEMM ----
    gemm_kernel<false, true, false, true, true, true><<<dim3(2, 16, B_), 256>>>(
        w3s, P_, 0, attout, NSP, (long)P_ * NSP, P_,
        wscs, CIN, 0, 0, x, NSP, (long)CIN * NSP, CIN,
        out, (long)COUT * NSP, nullptr, tfin);
}